// round 14
// baseline (speedup 1.0000x reference)
#include <cuda_runtime.h>
#include <cuda_bf16.h>
#include <cstdint>

#define B_  4
#define S_  2048
#define D_  1024
#define H_  16
#define DK_ 10
#define DV_ 12
#define HK  (H_*DV_)      // 192
#define PAD 16            // padded row width for q scratch
#define KVP 12            // row width for k/v scratch (48B rows, 16B-aligned)
#define NW  192           // packed N per section
#define KSPLIT 4          // key-dimension split for attention

typedef unsigned long long ull;

// ---------------- scratch (device globals; no allocation allowed) ----------
__device__ __nv_bfloat16 g_wbh[3*D_*NW];    // [sec][d][n] bf16 hi (QKV proj W)
__device__ __nv_bfloat16 g_wbl[3*D_*NW];    // [sec][d][n] bf16 lo
__device__ __nv_bfloat16 g_wobh[HK*D_];     // [k][n] bf16 hi (WO)
__device__ __nv_bfloat16 g_wobl[HK*D_];     // [k][n] bf16 lo
__device__ float g_q[B_*H_*S_*PAD];         // [bh][s][16] (10 valid)
__device__ float g_k[B_*H_*S_*KVP];         // [bh][s][12] (10 valid)
__device__ float g_v[B_*H_*S_*KVP];         // [bh][s][12]
__device__ float g_part[KSPLIT*B_*H_*S_*16]; // [g][bh][s][16]: 12 num + den
__device__ float g_heads[B_*S_*HK];         // [b*s][192]

// ---------------- packed f32x2 helpers ------------------------------------
__device__ __forceinline__ ull pk2(float lo, float hi) {
    ull r; asm("mov.b64 %0, {%1,%2};" : "=l"(r) : "f"(lo), "f"(hi)); return r;
}
__device__ __forceinline__ ull fma2(ull a, ull b, ull c) {
    ull d; asm("fma.rn.f32x2 %0, %1, %2, %3;" : "=l"(d) : "l"(a), "l"(b), "l"(c)); return d;
}
__device__ __forceinline__ ull mul2(ull a, ull b) {
    ull d; asm("mul.rn.f32x2 %0, %1, %2;" : "=l"(d) : "l"(a), "l"(b)); return d;
}
__device__ __forceinline__ float2 upk2(ull v) {
    float2 r; asm("mov.b64 {%0,%1}, %2;" : "=f"(r.x), "=f"(r.y) : "l"(v)); return r;
}
__device__ __forceinline__ float ex2(float x) {
    float r; asm("ex2.approx.f32 %0, %1;" : "=f"(r) : "f"(x)); return r;
}

// ---------------- cp.async helpers (sm_80 baseline PTX) --------------------
__device__ __forceinline__ void cp16(uint32_t dst, const void* src) {
    asm volatile("cp.async.cg.shared.global [%0], [%1], 16;" :: "r"(dst), "l"(src));
}
#define CP_COMMIT() asm volatile("cp.async.commit_group;" ::: "memory")
#define CP_WAIT(n)  asm volatile("cp.async.wait_group %0;" :: "n"(n) : "memory")

// ---------------- legacy tensor helpers (baseline PTX, sm_80-era) ---------
__device__ __forceinline__ uint32_t smem_u32(const void* p) {
    uint32_t a;
    asm("{ .reg .u64 t; cvta.to.shared.u64 t, %1; cvt.u32.u64 %0, t; }" : "=r"(a) : "l"(p));
    return a;
}
__device__ __forceinline__ void ldmx4(uint32_t* r, uint32_t a) {
    asm volatile("ldmatrix.sync.aligned.m8n8.x4.shared.b16 {%0,%1,%2,%3}, [%4];"
                 : "=r"(r[0]), "=r"(r[1]), "=r"(r[2]), "=r"(r[3]) : "r"(a));
}
__device__ __forceinline__ void ldmx4t(uint32_t* r, uint32_t a) {
    asm volatile("ldmatrix.sync.aligned.m8n8.x4.trans.shared.b16 {%0,%1,%2,%3}, [%4];"
                 : "=r"(r[0]), "=r"(r[1]), "=r"(r[2]), "=r"(r[3]) : "r"(a));
}
__device__ __forceinline__ void mma16816(float* c, const uint32_t* a,
                                         uint32_t b0, uint32_t b1) {
    asm volatile(
        "mma.sync.aligned.m16n8k16.row.col.f32.bf16.bf16.f32 "
        "{%0,%1,%2,%3}, {%4,%5,%6,%7}, {%8,%9}, {%0,%1,%2,%3};"
        : "+f"(c[0]), "+f"(c[1]), "+f"(c[2]), "+f"(c[3])
        : "r"(a[0]), "r"(a[1]), "r"(a[2]), "r"(a[3]), "r"(b0), "r"(b1));
}
__device__ __forceinline__ uint32_t bf2u(__nv_bfloat162 v) {
    return *reinterpret_cast<uint32_t*>(&v);
}

// ==========================================================================
// Kernel 0a: pack QKV weights -> bf16 hi/lo, [sec][d][n], n = h*12+j.
// ==========================================================================
__global__ void pack_w_kernel(const float* __restrict__ WQ,
                              const float* __restrict__ WK,
                              const float* __restrict__ WV)
{
    int idx = blockIdx.x * 256 + threadIdx.x;   // 0 .. 3*1024*192-1
    int sec = idx / (D_ * NW);
    int rem = idx - sec * (D_ * NW);
    int d   = rem / NW;
    int n   = rem - d * NW;
    int h   = n / 12, j = n - h * 12;
    float v = 0.f;
    if (sec == 0)      { if (j < DK_) v = WQ[(h * D_ + d) * DK_ + j]; }
    else if (sec == 1) { if (j < DK_) v = WK[(h * D_ + d) * DK_ + j]; }
    else               {              v = WV[(h * D_ + d) * DV_ + j]; }
    __nv_bfloat16 hi = __float2bfloat16(v);
    __nv_bfloat16 lo = __float2bfloat16(v - __bfloat162float(hi));
    g_wbh[idx] = hi;
    g_wbl[idx] = lo;
}

// ==========================================================================
// Kernel 0b: pack WO[192,1024] -> bf16 hi/lo (row-major, as stored).
// ==========================================================================
__global__ void pack_wo_kernel(const float* __restrict__ WO)
{
    int idx = blockIdx.x * 256 + threadIdx.x;   // 0 .. 192*1024-1
    float v = WO[idx];
    __nv_bfloat16 hi = __float2bfloat16(v);
    __nv_bfloat16 lo = __float2bfloat16(v - __bfloat162float(hi));
    g_wobh[idx] = hi;
    g_wobl[idx] = lo;
}

// ==========================================================================
// Kernel 1: projection GEMM on legacy tensor cores (mma.sync bf16, 2-word
// split: ah*bh + ah*bl + al*bh). C tile 64x192 per CTA, BK=32, 4 warps.
// Epilogue writes Q rows at stride 16, K/V rows at stride 12.
// ==========================================================================
__global__ void __launch_bounds__(128, 3)
proj_mma_kernel(const float* __restrict__ Qi,
                const float* __restrict__ Ki,
                const float* __restrict__ Vi)
{
    const int z  = blockIdx.y;
    const float* A = (z == 0) ? Qi : (z == 1) ? Ki : Vi;
    const int m0 = blockIdx.x * 64;
    const int tid  = threadIdx.x;     // 128
    const int w    = tid >> 5;
    const int lane = tid & 31;

    __shared__ __align__(16) __nv_bfloat16 Ah[64][40];   // 80B stride
    __shared__ __align__(16) __nv_bfloat16 Al[64][40];
    __shared__ __align__(16) __nv_bfloat16 Bh[32][200];  // 400B stride
    __shared__ __align__(16) __nv_bfloat16 Bl[32][200];

    const uint32_t AhB = smem_u32(&Ah[0][0]);
    const uint32_t AlB = smem_u32(&Al[0][0]);
    const uint32_t BhB = smem_u32(&Bh[0][0]);
    const uint32_t BlB = smem_u32(&Bl[0][0]);

    float acc[24][4];
    #pragma unroll
    for (int t = 0; t < 24; t++)
        #pragma unroll
        for (int u = 0; u < 4; u++) acc[t][u] = 0.f;

    const __nv_bfloat16* wbh = g_wbh + (size_t)z * D_ * NW;
    const __nv_bfloat16* wbl = g_wbl + (size_t)z * D_ * NW;

    for (int k0 = 0; k0 < D_; k0 += 32) {
        #pragma unroll
        for (int l = 0; l < 4; l++) {
            int f   = tid + l * 128;
            int row = f >> 3, c4 = f & 7;
            float4 a = *(const float4*)(A + (size_t)(m0 + row) * D_ + k0 + c4 * 4);
            __nv_bfloat16 hx = __float2bfloat16(a.x), hy = __float2bfloat16(a.y);
            __nv_bfloat16 hz = __float2bfloat16(a.z), hw = __float2bfloat16(a.w);
            __nv_bfloat16 lx = __float2bfloat16(a.x - __bfloat162float(hx));
            __nv_bfloat16 ly = __float2bfloat16(a.y - __bfloat162float(hy));
            __nv_bfloat16 lz = __float2bfloat16(a.z - __bfloat162float(hz));
            __nv_bfloat16 lw = __float2bfloat16(a.w - __bfloat162float(hw));
            *(uint32_t*)&Ah[row][c4 * 4 + 0] = bf2u(__nv_bfloat162(hx, hy));
            *(uint32_t*)&Ah[row][c4 * 4 + 2] = bf2u(__nv_bfloat162(hz, hw));
            *(uint32_t*)&Al[row][c4 * 4 + 0] = bf2u(__nv_bfloat162(lx, ly));
            *(uint32_t*)&Al[row][c4 * 4 + 2] = bf2u(__nv_bfloat162(lz, lw));
        }
        #pragma unroll
        for (int l = 0; l < 6; l++) {
            int idx = tid + l * 128;        // 0..767
            int kk  = idx / 24;
            int u   = idx - kk * 24;
            *(uint4*)&Bh[kk][u * 8] = *(const uint4*)(wbh + (size_t)(k0 + kk) * NW + u * 8);
            *(uint4*)&Bl[kk][u * 8] = *(const uint4*)(wbl + (size_t)(k0 + kk) * NW + u * 8);
        }
        __syncthreads();

        #pragma unroll
        for (int ks = 0; ks < 2; ks++) {
            uint32_t aoff = (uint32_t)(w * 16 + (lane & 15)) * 80
                          + (uint32_t)(ks * 16 + (lane >> 4) * 8) * 2;
            uint32_t ah[4], al[4];
            ldmx4(ah, AhB + aoff);
            ldmx4(al, AlB + aoff);

            uint32_t brow = (uint32_t)(ks * 16 + ((lane >> 3) & 1) * 8 + (lane & 7));
            uint32_t bbase = brow * 400 + (uint32_t)(lane >> 4) * 16;

            #pragma unroll
            for (int nt = 0; nt < 12; nt++) {
                uint32_t bh[4], bl[4];
                ldmx4t(bh, BhB + bbase + nt * 32);
                ldmx4t(bl, BlB + bbase + nt * 32);
                mma16816(acc[nt * 2 + 0], ah, bh[0], bh[1]);
                mma16816(acc[nt * 2 + 0], al, bh[0], bh[1]);
                mma16816(acc[nt * 2 + 0], ah, bl[0], bl[1]);
                mma16816(acc[nt * 2 + 1], ah, bh[2], bh[3]);
                mma16816(acc[nt * 2 + 1], al, bh[2], bh[3]);
                mma16816(acc[nt * 2 + 1], ah, bl[2], bl[3]);
            }
        }
        __syncthreads();
    }

    // ---- epilogue: frag (c0,c1)@row r, (c2,c3)@row r+8; scatter ----
    const int b  = m0 >> 11;
    const int s0 = (m0 & 2047) + w * 16 + (lane >> 2);
    const int lc = lane & 3;
    #pragma unroll
    for (int t = 0; t < 24; t++) {
        int n = t * 8 + lc * 2;          // even -> (n, n+1) same head
        int h = n / 12, j = n - h * 12;
        if (z == 0) {
            float* o = g_q + ((size_t)(b * H_ + h) * S_ + s0) * PAD + j;
            *(float2*)o             = make_float2(acc[t][0], acc[t][1]);
            *(float2*)(o + 8 * PAD) = make_float2(acc[t][2], acc[t][3]);
        } else {
            float* base = (z == 1) ? g_k : g_v;
            float* o = base + ((size_t)(b * H_ + h) * S_ + s0) * KVP + j;
            *(float2*)o             = make_float2(acc[t][0], acc[t][1]);
            *(float2*)(o + 8 * KVP) = make_float2(acc[t][2], acc[t][3]);
        }
    }
}

// ==========================================================================
// Kernel 2: streaming attention, key-split x4, cp.async double-buffered
// 48B K/V rows (smem 25KB -> 7 CTAs/SM). 128 thr, 2 queries/thread.
// ==========================================================================
#define TK 128
#define NT ((S_ / KSPLIT) / TK)   // 4 tiles per CTA

__global__ void __launch_bounds__(128, 7) attn_kernel()
{
    const int bh  = blockIdx.x;
    const int q0  = blockIdx.y * 256;
    const int z   = blockIdx.z;        // key quarter
    const int tid = threadIdx.x;

    const float scale2 = 0.45622024f;   // (1/sqrt(10)) * log2(e)

    ull qa[5], qb[5];
    {
        const float* pa = g_q + ((size_t)bh * S_ + q0 + tid) * PAD;
        const float* pb = pa + (size_t)128 * PAD;
        #pragma unroll
        for (int u = 0; u < 5; u++) {
            qa[u] = pk2(pa[2 * u] * scale2, pa[2 * u + 1] * scale2);
            qb[u] = pk2(pb[2 * u] * scale2, pb[2 * u + 1] * scale2);
        }
    }

    __shared__ __align__(16) float Ks[2][TK][KVP];
    __shared__ __align__(16) float Vs[2][TK][KVP];
    const uint32_t KsB = smem_u32(&Ks[0][0][0]);
    const uint32_t VsB = smem_u32(&Vs[0][0][0]);

    ull acca[6] = {0,0,0,0,0,0};
    ull accb[6] = {0,0,0,0,0,0};
    float dena = 0.f, denb = 0.f;

    const float* kbase = g_k + (size_t)bh * S_ * KVP;
    const float* vbase = g_v + (size_t)bh * S_ * KVP;
    const int t_lo = z * (S_ / KSPLIT);

    // issue cp.async for one tile (48B of K row + 48B of V row per thread)
    auto issue_tile = [&](int trow, int buf) {
        const float* kr = kbase + (size_t)(trow + tid) * KVP;
        const float* vr = vbase + (size_t)(trow + tid) * KVP;
        uint32_t kd = KsB + (uint32_t)(buf * TK + tid) * (KVP * 4);
        uint32_t vd = VsB + (uint32_t)(buf * TK + tid) * (KVP * 4);
        cp16(kd,      kr);     cp16(kd + 16, kr + 4); cp16(kd + 32, kr + 8);
        cp16(vd,      vr);     cp16(vd + 16, vr + 4); cp16(vd + 32, vr + 8);
        CP_COMMIT();
    };

    issue_tile(t_lo, 0);

    for (int ti = 0; ti < NT; ti++) {
        if (ti + 1 < NT) {
            issue_tile(t_lo + (ti + 1) * TK, (ti + 1) & 1);
            CP_WAIT(1);
        } else {
            CP_WAIT(0);
        }
        __syncthreads();

        const float (*Kb)[KVP] = Ks[ti & 1];
        const float (*Vb)[KVP] = Vs[ti & 1];

        #pragma unroll 8
        for (int j = 0; j < TK; j++) {
            ulonglong2 k01 = *(const ulonglong2*)&Kb[j][0];
            ulonglong2 k23 = *(const ulonglong2*)&Kb[j][4];
            ull        k4  = *(const ull*)&Kb[j][8];

            ull sa2 = mul2(qa[0], k01.x);
            ull sb2 = mul2(qb[0], k01.x);
            sa2 = fma2(qa[1], k01.y, sa2);  sb2 = fma2(qb[1], k01.y, sb2);
            sa2 = fma2(qa[2], k23.x, sa2);  sb2 = fma2(qb[2], k23.x, sb2);
            sa2 = fma2(qa[3], k23.y, sa2);  sb2 = fma2(qb[3], k23.y, sb2);
            sa2 = fma2(qa[4], k4,   sa2);   sb2 = fma2(qb[4], k4,   sb2);
            float2 fa = upk2(sa2), fb = upk2(sb2);
            float pa = ex2(fa.x + fa.y);
            float pb = ex2(fb.x + fb.y);
            dena += pa; denb += pb;
            ull ppa = pk2(pa, pa), ppb = pk2(pb, pb);

            ulonglong2 v01 = *(const ulonglong2*)&Vb[j][0];
            ulonglong2 v23 = *(const ulonglong2*)&Vb[j][4];
            ulonglong2 v45 = *(const ulonglong2*)&Vb[j][8];
            acca[0] = fma2(ppa, v01.x, acca[0]);  accb[0] = fma2(ppb, v01.x, accb[0]);
            acca[1] = fma2(ppa, v01.y, acca[1]);  accb[1] = fma2(ppb, v01.y, accb[1]);
            acca[2] = fma2(ppa, v23.x, acca[2]);  accb[2] = fma2(ppb, v23.x, accb[2]);
            acca[3] = fma2(ppa, v23.y, acca[3]);  accb[3] = fma2(ppb, v23.y, accb[3]);
            acca[4] = fma2(ppa, v45.x, acca[4]);  accb[4] = fma2(ppb, v45.x, accb[4]);
            acca[5] = fma2(ppa, v45.y, acca[5]);  accb[5] = fma2(ppb, v45.y, accb[5]);
        }
        __syncthreads();
    }

    // write partials: [z][bh][s][16] = 12 num + den (+3 pad)
    float* oa = g_part + (((size_t)z * (B_ * H_) + bh) * S_ + (q0 + tid)) * 16;
    float* ob = oa + (size_t)128 * 16;
    {
        float2 r0 = upk2(acca[0]), r1 = upk2(acca[1]), r2 = upk2(acca[2]);
        float2 r3 = upk2(acca[3]), r4 = upk2(acca[4]), r5 = upk2(acca[5]);
        *(float4*)(oa + 0)  = make_float4(r0.x, r0.y, r1.x, r1.y);
        *(float4*)(oa + 4)  = make_float4(r2.x, r2.y, r3.x, r3.y);
        *(float4*)(oa + 8)  = make_float4(r4.x, r4.y, r5.x, r5.y);
        *(float4*)(oa + 12) = make_float4(dena, 0.f, 0.f, 0.f);
    }
    {
        float2 r0 = upk2(accb[0]), r1 = upk2(accb[1]), r2 = upk2(accb[2]);
        float2 r3 = upk2(accb[3]), r4 = upk2(accb[4]), r5 = upk2(accb[5]);
        *(float4*)(ob + 0)  = make_float4(r0.x, r0.y, r1.x, r1.y);
        *(float4*)(ob + 4)  = make_float4(r2.x, r2.y, r3.x, r3.y);
        *(float4*)(ob + 8)  = make_float4(r4.x, r4.y, r5.x, r5.y);
        *(float4*)(ob + 12) = make_float4(denb, 0.f, 0.f, 0.f);
    }
}

// ==========================================================================
// Kernel 2b: reduce KSPLIT partials -> g_heads (divide by total den).
// ==========================================================================
__global__ void attn_reduce_kernel()
{
    int idx = blockIdx.x * 256 + threadIdx.x;   // 0 .. 64*2048-1
    int bh = idx >> 11;
    int s  = idx & 2047;
    int b  = bh >> 4, h = bh & 15;

    const size_t zstride = (size_t)(B_ * H_) * S_ * 16;
    const float* r0 = g_part + ((size_t)bh * S_ + s) * 16;

    float n0 = 0.f, n1 = 0.f, n2 = 0.f, n3 = 0.f;
    float n4 = 0.f, n5 = 0.f, n6 = 0.f, n7 = 0.f;
    float n8 = 0.f, n9 = 0.f, n10 = 0.f, n11 = 0.f;
    float den = 0.f;
    #pragma unroll
    for (int zz = 0; zz < KSPLIT; zz++) {
        const float* r = r0 + zz * zstride;
        float4 a0 = *(const float4*)(r + 0);
        float4 a1 = *(const float4*)(r + 4);
        float4 a2 = *(const float4*)(r + 8);
        n0 += a0.x; n1 += a0.y; n2  += a0.z; n3  += a0.w;
        n4 += a1.x; n5 += a1.y; n6  += a1.z; n7  += a1.w;
        n8 += a2.x; n9 += a2.y; n10 += a2.z; n11 += a2.w;
        den += r[12];
    }

    float inv = 1.f / den;
    float* o = g_heads + ((size_t)(b * S_ + s)) * HK + h * DV_;
    *(float4*)(o + 0) = make_float4(n0 * inv, n1 * inv, n2 * inv, n3 * inv);
    *(float4*)(o + 4) = make_float4(n4 * inv, n5 * inv, n6 * inv, n7 * inv);
    *(float4*)(o + 8) = make_float4(n8 * inv, n9 * inv, n10 * inv, n11 * inv);
}

// ==========================================================================
// Kernel 3: output projection on legacy tensor cores (R10 config).
// ==========================================================================
__global__ void __launch_bounds__(128, 4)
outproj_mma_kernel(float* __restrict__ out)
{
    const int m0 = blockIdx.x * 64;
    const int n0 = blockIdx.y * 128;
    const int tid  = threadIdx.x;     // 128
    const int w    = tid >> 5;
    const int lane = tid & 31;

    __shared__ __align__(16) __nv_bfloat16 Ah[64][40];   // 80B stride
    __shared__ __align__(16) __nv_bfloat16 Al[64][40];
    __shared__ __align__(16) __nv_bfloat16 Bh[32][136];  // 272B stride
    __shared__ __align__(16) __nv_bfloat16 Bl[32][136];

    const uint32_t AhB = smem_u32(&Ah[0][0]);
    const uint32_t AlB = smem_u32(&Al[0][0]);
    const uint32_t BhB = smem_u32(&Bh[0][0]);
    const uint32_t BlB = smem_u32(&Bl[0][0]);

    float acc[16][4];
    #pragma unroll
    for (int t = 0; t < 16; t++)
        #pragma unroll
        for (int u = 0; u < 4; u++) acc[t][u] = 0.f;

    for (int k0 = 0; k0 < HK; k0 += 32) {
        #pragma unroll
        for (int l = 0; l < 4; l++) {
            int f   = tid + l * 128;
            int row = f >> 3, c4 = f & 7;
            float4 a = *(const float4*)(g_heads + (size_t)(m0 + row) * HK + k0 + c4 * 4);
            __nv_bfloat16 hx = __float2bfloat16(a.x), hy = __float2bfloat16(a.y);
            __nv_bfloat16 hz = __float2bfloat16(a.z), hw = __float2bfloat16(a.w);
            __nv_bfloat16 lx = __float2bfloat16(a.x - __bfloat162float(hx));
            __nv_bfloat16 ly = __float2bfloat16(a.y - __bfloat162float(hy));
            __nv_bfloat16 lz = __float2bfloat16(a.z - __bfloat162float(hz));
            __nv_bfloat16 lw = __float2bfloat16(a.w - __bfloat162float(hw));
            *(uint32_t*)&Ah[row][c4 * 4 + 0] = bf2u(__nv_bfloat162(hx, hy));
            *(uint32_t*)&Ah[row][c4 * 4 + 2] = bf2u(__nv_bfloat162(hz, hw));
            *(uint32_t*)&Al[row][c4 * 4 + 0] = bf2u(__nv_bfloat162(lx, ly));
            *(uint32_t*)&Al[row][c4 * 4 + 2] = bf2u(__nv_bfloat162(lz, lw));
        }
        #pragma unroll
        for (int l = 0; l < 4; l++) {
            int idx = tid + l * 128;        // 0..511
            int kk  = idx >> 4;             // 16 uint4 per row
            int u   = idx & 15;
            *(uint4*)&Bh[kk][u * 8] = *(const uint4*)(g_wobh + (size_t)(k0 + kk) * D_ + n0 + u * 8);
            *(uint4*)&Bl[kk][u * 8] = *(const uint4*)(g_wobl + (size_t)(k0 + kk) * D_ + n0 + u * 8);
        }
        __syncthreads();

        #pragma unroll
        for (int ks = 0; ks < 2; ks++) {
            uint32_t aoff = (uint32_t)(w * 16 + (lane & 15)) * 80
                          + (uint32_t)(ks * 16 + (lane >> 4) * 8) * 2;
            uint32_t ah[4], al[4];
            ldmx4(ah, AhB + aoff);
            ldmx4(al, AlB + aoff);

            uint32_t brow = (uint32_t)(ks * 16 + ((lane >> 3) & 1) * 8 + (lane & 7));
            uint32_t bbase = brow * 272 + (uint32_t)(lane >> 4) * 16;

            #pragma unroll
            for (int nt = 0; nt < 8; nt++) {
                uint32_t bh[4], bl[4];
                ldmx4t(bh, BhB + bbase + nt * 32);
                ldmx4t(bl, BlB + bbase + nt * 32);
                mma16816(acc[nt * 2 + 0], ah, bh[0], bh[1]);
                mma16816(acc[nt * 2 + 0], al, bh[0], bh[1]);
                mma16816(acc[nt * 2 + 0], ah, bl[0], bl[1]);
                mma16816(acc[nt * 2 + 1], ah, bh[2], bh[3]);
                mma16816(acc[nt * 2 + 1], al, bh[2], bh[3]);
                mma16816(acc[nt * 2 + 1], ah, bl[2], bl[3]);
            }
        }
        __syncthreads();
    }

    const int r0 = m0 + w * 16 + (lane >> 2);
    const int lc = lane & 3;
    #pragma unroll
    for (int t = 0; t < 16; t++) {
        int n = n0 + t * 8 + lc * 2;
        float* o = out + (size_t)r0 * D_ + n;
        *(float2*)o            = make_float2(acc[t][0], acc[t][1]);
        *(float2*)(o + 8 * D_) = make_float2(acc[t][2], acc[t][3]);
    }
}

// ==========================================================================
extern "C" void kernel_launch(void* const* d_in, const int* in_sizes, int n_in,
                              void* d_out, int out_size)
{
    const float* Q  = (const float*)d_in[0];
    const float* K  = (const float*)d_in[1];
    const float* V  = (const float*)d_in[2];
    const float* WQ = (const float*)d_in[3];
    const float* WK = (const float*)d_in[4];
    const float* WV = (const float*)d_in[5];
    const float* WO = (const float*)d_in[6];
    float* out = (float*)d_out;

    pack_w_kernel<<<(3 * D_ * NW) / 256, 256>>>(WQ, WK, WV);
    pack_wo_kernel<<<(HK * D_) / 256, 256>>>(WO);
    proj_mma_kernel<<<dim3(128, 3), 128>>>(Q, K, V);
    attn_kernel<<<dim3(B_ * H_, S_ / 256, KSPLIT), 128>>>();
    attn_reduce_kernel<<<(B_ * H_ * S_) / 256, 256>>>();
    outproj_mma_kernel<<<dim3((B_ * S_) / 64, D_ / 128), 128>>>(out);
}

// round 15
// speedup vs baseline: 1.0279x; 1.0279x over previous
#include <cuda_runtime.h>
#include <cuda_bf16.h>
#include <cstdint>

#define B_  4
#define S_  2048
#define D_  1024
#define H_  16
#define DK_ 10
#define DV_ 12
#define HK  (H_*DV_)      // 192
#define PAD 16            // padded row width for q/k/v scratch
#define NW  192           // packed N per section
#define KSPLIT 4          // key-dimension split for attention

typedef unsigned long long ull;

// ---------------- scratch (device globals; no allocation allowed) ----------
__device__ __nv_bfloat16 g_wbh[3*D_*NW];    // [sec][d][n] bf16 hi (QKV proj W)
__device__ __nv_bfloat16 g_wbl[3*D_*NW];    // [sec][d][n] bf16 lo
__device__ __nv_bfloat16 g_wobh[HK*D_];     // [k][n] bf16 hi (WO)
__device__ __nv_bfloat16 g_wobl[HK*D_];     // [k][n] bf16 lo
__device__ float g_q[B_*H_*S_*PAD];         // [bh][s][16] (10 valid)
__device__ float g_k[B_*H_*S_*PAD];         // [bh][s][16] (10 valid)
__device__ float g_v[B_*H_*S_*PAD];         // [bh][s][16] (12 valid)
__device__ float g_part[KSPLIT*B_*H_*S_*16]; // [g][bh][s][16]: 12 num + den
__device__ float g_heads[B_*S_*HK];         // [b*s][192]

// ---------------- packed f32x2 helpers ------------------------------------
__device__ __forceinline__ ull pk2(float lo, float hi) {
    ull r; asm("mov.b64 %0, {%1,%2};" : "=l"(r) : "f"(lo), "f"(hi)); return r;
}
__device__ __forceinline__ ull fma2(ull a, ull b, ull c) {
    ull d; asm("fma.rn.f32x2 %0, %1, %2, %3;" : "=l"(d) : "l"(a), "l"(b), "l"(c)); return d;
}
__device__ __forceinline__ ull mul2(ull a, ull b) {
    ull d; asm("mul.rn.f32x2 %0, %1, %2;" : "=l"(d) : "l"(a), "l"(b)); return d;
}
__device__ __forceinline__ float2 upk2(ull v) {
    float2 r; asm("mov.b64 {%0,%1}, %2;" : "=f"(r.x), "=f"(r.y) : "l"(v)); return r;
}
__device__ __forceinline__ float ex2(float x) {
    float r; asm("ex2.approx.f32 %0, %1;" : "=f"(r) : "f"(x)); return r;
}

// ---------------- cp.async helpers (sm_80 baseline PTX) --------------------
__device__ __forceinline__ void cp16(uint32_t dst, const void* src) {
    asm volatile("cp.async.cg.shared.global [%0], [%1], 16;" :: "r"(dst), "l"(src));
}
#define CP_COMMIT() asm volatile("cp.async.commit_group;" ::: "memory")
#define CP_WAIT(n)  asm volatile("cp.async.wait_group %0;" :: "n"(n) : "memory")

// ---------------- legacy tensor helpers (baseline PTX, sm_80-era) ---------
__device__ __forceinline__ uint32_t smem_u32(const void* p) {
    uint32_t a;
    asm("{ .reg .u64 t; cvta.to.shared.u64 t, %1; cvt.u32.u64 %0, t; }" : "=r"(a) : "l"(p));
    return a;
}
__device__ __forceinline__ void ldmx4(uint32_t* r, uint32_t a) {
    asm volatile("ldmatrix.sync.aligned.m8n8.x4.shared.b16 {%0,%1,%2,%3}, [%4];"
                 : "=r"(r[0]), "=r"(r[1]), "=r"(r[2]), "=r"(r[3]) : "r"(a));
}
__device__ __forceinline__ void ldmx4t(uint32_t* r, uint32_t a) {
    asm volatile("ldmatrix.sync.aligned.m8n8.x4.trans.shared.b16 {%0,%1,%2,%3}, [%4];"
                 : "=r"(r[0]), "=r"(r[1]), "=r"(r[2]), "=r"(r[3]) : "r"(a));
}
__device__ __forceinline__ void mma16816(float* c, const uint32_t* a,
                                         uint32_t b0, uint32_t b1) {
    asm volatile(
        "mma.sync.aligned.m16n8k16.row.col.f32.bf16.bf16.f32 "
        "{%0,%1,%2,%3}, {%4,%5,%6,%7}, {%8,%9}, {%0,%1,%2,%3};"
        : "+f"(c[0]), "+f"(c[1]), "+f"(c[2]), "+f"(c[3])
        : "r"(a[0]), "r"(a[1]), "r"(a[2]), "r"(a[3]), "r"(b0), "r"(b1));
}
__device__ __forceinline__ uint32_t bf2u(__nv_bfloat162 v) {
    return *reinterpret_cast<uint32_t*>(&v);
}

// ==========================================================================
// Kernel 0a: pack QKV weights -> bf16 hi/lo, [sec][d][n], n = h*12+j.
// ==========================================================================
__global__ void pack_w_kernel(const float* __restrict__ WQ,
                              const float* __restrict__ WK,
                              const float* __restrict__ WV)
{
    int idx = blockIdx.x * 256 + threadIdx.x;   // 0 .. 3*1024*192-1
    int sec = idx / (D_ * NW);
    int rem = idx - sec * (D_ * NW);
    int d   = rem / NW;
    int n   = rem - d * NW;
    int h   = n / 12, j = n - h * 12;
    float v = 0.f;
    if (sec == 0)      { if (j < DK_) v = WQ[(h * D_ + d) * DK_ + j]; }
    else if (sec == 1) { if (j < DK_) v = WK[(h * D_ + d) * DK_ + j]; }
    else               {              v = WV[(h * D_ + d) * DV_ + j]; }
    __nv_bfloat16 hi = __float2bfloat16(v);
    __nv_bfloat16 lo = __float2bfloat16(v - __bfloat162float(hi));
    g_wbh[idx] = hi;
    g_wbl[idx] = lo;
}

// ==========================================================================
// Kernel 0b: pack WO[192,1024] -> bf16 hi/lo (row-major, as stored).
// ==========================================================================
__global__ void pack_wo_kernel(const float* __restrict__ WO)
{
    int idx = blockIdx.x * 256 + threadIdx.x;   // 0 .. 192*1024-1
    float v = WO[idx];
    __nv_bfloat16 hi = __float2bfloat16(v);
    __nv_bfloat16 lo = __float2bfloat16(v - __bfloat162float(hi));
    g_wobh[idx] = hi;
    g_wobl[idx] = lo;
}

// ==========================================================================
// Kernel 1: projection GEMM on legacy tensor cores (mma.sync bf16, 2-word
// split: ah*bh + ah*bl + al*bh). C tile 64x192 per CTA, BK=32, 4 warps.
// B tiles streamed via cp.async (pure bf16 copy) overlapping the A-convert.
// ==========================================================================
__global__ void __launch_bounds__(128, 3)
proj_mma_kernel(const float* __restrict__ Qi,
                const float* __restrict__ Ki,
                const float* __restrict__ Vi)
{
    const int z  = blockIdx.y;
    const float* A = (z == 0) ? Qi : (z == 1) ? Ki : Vi;
    const int m0 = blockIdx.x * 64;
    const int tid  = threadIdx.x;     // 128
    const int w    = tid >> 5;
    const int lane = tid & 31;

    __shared__ __align__(16) __nv_bfloat16 Ah[64][40];   // 80B stride
    __shared__ __align__(16) __nv_bfloat16 Al[64][40];
    __shared__ __align__(16) __nv_bfloat16 Bh[32][200];  // 400B stride
    __shared__ __align__(16) __nv_bfloat16 Bl[32][200];

    const uint32_t AhB = smem_u32(&Ah[0][0]);
    const uint32_t AlB = smem_u32(&Al[0][0]);
    const uint32_t BhB = smem_u32(&Bh[0][0]);
    const uint32_t BlB = smem_u32(&Bl[0][0]);

    float acc[24][4];
    #pragma unroll
    for (int t = 0; t < 24; t++)
        #pragma unroll
        for (int u = 0; u < 4; u++) acc[t][u] = 0.f;

    const __nv_bfloat16* wbh = g_wbh + (size_t)z * D_ * NW;
    const __nv_bfloat16* wbl = g_wbl + (size_t)z * D_ * NW;

    // cp.async slot assignment: 6 rows per thread (kk = idx/24, u = idx%24)
    for (int k0 = 0; k0 < D_; k0 += 32) {
        // ---- B tiles via cp.async (overlaps with A conversion below) ----
        #pragma unroll
        for (int l = 0; l < 6; l++) {
            int idx = tid + l * 128;        // 0..767
            int kk  = idx / 24;
            int u   = idx - kk * 24;
            cp16(BhB + (uint32_t)kk * 400 + (uint32_t)u * 16,
                 wbh + (size_t)(k0 + kk) * NW + u * 8);
            cp16(BlB + (uint32_t)kk * 400 + (uint32_t)u * 16,
                 wbl + (size_t)(k0 + kk) * NW + u * 8);
        }
        CP_COMMIT();

        // ---- stage A: 64x32 f32 -> bf16 hi/lo. 512 f4, 4/thread ----
        #pragma unroll
        for (int l = 0; l < 4; l++) {
            int f   = tid + l * 128;
            int row = f >> 3, c4 = f & 7;
            float4 a = *(const float4*)(A + (size_t)(m0 + row) * D_ + k0 + c4 * 4);
            __nv_bfloat16 hx = __float2bfloat16(a.x), hy = __float2bfloat16(a.y);
            __nv_bfloat16 hz = __float2bfloat16(a.z), hw = __float2bfloat16(a.w);
            __nv_bfloat16 lx = __float2bfloat16(a.x - __bfloat162float(hx));
            __nv_bfloat16 ly = __float2bfloat16(a.y - __bfloat162float(hy));
            __nv_bfloat16 lz = __float2bfloat16(a.z - __bfloat162float(hz));
            __nv_bfloat16 lw = __float2bfloat16(a.w - __bfloat162float(hw));
            *(uint32_t*)&Ah[row][c4 * 4 + 0] = bf2u(__nv_bfloat162(hx, hy));
            *(uint32_t*)&Ah[row][c4 * 4 + 2] = bf2u(__nv_bfloat162(hz, hw));
            *(uint32_t*)&Al[row][c4 * 4 + 0] = bf2u(__nv_bfloat162(lx, ly));
            *(uint32_t*)&Al[row][c4 * 4 + 2] = bf2u(__nv_bfloat162(lz, lw));
        }
        CP_WAIT(0);
        __syncthreads();

        #pragma unroll
        for (int ks = 0; ks < 2; ks++) {
            uint32_t aoff = (uint32_t)(w * 16 + (lane & 15)) * 80
                          + (uint32_t)(ks * 16 + (lane >> 4) * 8) * 2;
            uint32_t ah[4], al[4];
            ldmx4(ah, AhB + aoff);
            ldmx4(al, AlB + aoff);

            uint32_t brow = (uint32_t)(ks * 16 + ((lane >> 3) & 1) * 8 + (lane & 7));
            uint32_t bbase = brow * 400 + (uint32_t)(lane >> 4) * 16;

            #pragma unroll
            for (int nt = 0; nt < 12; nt++) {
                uint32_t bh[4], bl[4];
                ldmx4t(bh, BhB + bbase + nt * 32);
                ldmx4t(bl, BlB + bbase + nt * 32);
                mma16816(acc[nt * 2 + 0], ah, bh[0], bh[1]);
                mma16816(acc[nt * 2 + 0], al, bh[0], bh[1]);
                mma16816(acc[nt * 2 + 0], ah, bl[0], bl[1]);
                mma16816(acc[nt * 2 + 1], ah, bh[2], bh[3]);
                mma16816(acc[nt * 2 + 1], al, bh[2], bh[3]);
                mma16816(acc[nt * 2 + 1], ah, bl[2], bl[3]);
            }
        }
        __syncthreads();
    }

    // ---- epilogue: frag (c0,c1)@row r, (c2,c3)@row r+8; scatter padded ----
    const int b  = m0 >> 11;
    const int s0 = (m0 & 2047) + w * 16 + (lane >> 2);
    const int lc = lane & 3;
    float* base = (z == 0) ? g_q : (z == 1) ? g_k : g_v;
    #pragma unroll
    for (int t = 0; t < 24; t++) {
        int n = t * 8 + lc * 2;          // even -> (n, n+1) same head
        int h = n / 12, j = n - h * 12;
        float* o = base + ((size_t)(b * H_ + h) * S_ + s0) * PAD + j;
        *(float2*)o             = make_float2(acc[t][0], acc[t][1]);
        *(float2*)(o + 8 * PAD) = make_float2(acc[t][2], acc[t][3]);
    }
}

// ==========================================================================
// Kernel 2: streaming attention, key-split x4, cp.async double-buffered
// K/V tiles + unroll 8 (R13 known-good configuration).
// ==========================================================================
#define TK 128
#define NT ((S_ / KSPLIT) / TK)   // 4 tiles per CTA

__global__ void __launch_bounds__(128, 6) attn_kernel()
{
    const int bh  = blockIdx.x;
    const int q0  = blockIdx.y * 256;
    const int z   = blockIdx.z;        // key quarter
    const int tid = threadIdx.x;

    const float scale2 = 0.45622024f;   // (1/sqrt(10)) * log2(e)

    ull qa[5], qb[5];
    {
        const float* pa = g_q + ((size_t)bh * S_ + q0 + tid) * PAD;
        const float* pb = pa + (size_t)128 * PAD;
        #pragma unroll
        for (int u = 0; u < 5; u++) {
            qa[u] = pk2(pa[2 * u] * scale2, pa[2 * u + 1] * scale2);
            qb[u] = pk2(pb[2 * u] * scale2, pb[2 * u + 1] * scale2);
        }
    }

    __shared__ __align__(16) float Ks[2][TK][PAD];
    __shared__ __align__(16) float Vs[2][TK][PAD];
    const uint32_t KsB = smem_u32(&Ks[0][0][0]);
    const uint32_t VsB = smem_u32(&Vs[0][0][0]);

    ull acca[6] = {0,0,0,0,0,0};
    ull accb[6] = {0,0,0,0,0,0};
    float dena = 0.f, denb = 0.f;

    const float* kbase = g_k + (size_t)bh * S_ * PAD;
    const float* vbase = g_v + (size_t)bh * S_ * PAD;
    const int t_lo = z * (S_ / KSPLIT);

    auto issue_tile = [&](int trow, int buf) {
        const float* kr = kbase + (size_t)(trow + tid) * PAD;
        const float* vr = vbase + (size_t)(trow + tid) * PAD;
        uint32_t kd = KsB + (uint32_t)(buf * TK + tid) * (PAD * 4);
        uint32_t vd = VsB + (uint32_t)(buf * TK + tid) * (PAD * 4);
        cp16(kd,      kr);     cp16(kd + 16, kr + 4); cp16(kd + 32, kr + 8);
        cp16(vd,      vr);     cp16(vd + 16, vr + 4); cp16(vd + 32, vr + 8);
        CP_COMMIT();
    };

    issue_tile(t_lo, 0);

    for (int ti = 0; ti < NT; ti++) {
        if (ti + 1 < NT) {
            issue_tile(t_lo + (ti + 1) * TK, (ti + 1) & 1);
            CP_WAIT(1);
        } else {
            CP_WAIT(0);
        }
        __syncthreads();

        const float (*Kb)[PAD] = Ks[ti & 1];
        const float (*Vb)[PAD] = Vs[ti & 1];

        #pragma unroll 8
        for (int j = 0; j < TK; j++) {
            ulonglong2 k01 = *(const ulonglong2*)&Kb[j][0];
            ulonglong2 k23 = *(const ulonglong2*)&Kb[j][4];
            ull        k4  = *(const ull*)&Kb[j][8];

            ull sa2 = mul2(qa[0], k01.x);
            ull sb2 = mul2(qb[0], k01.x);
            sa2 = fma2(qa[1], k01.y, sa2);  sb2 = fma2(qb[1], k01.y, sb2);
            sa2 = fma2(qa[2], k23.x, sa2);  sb2 = fma2(qb[2], k23.x, sb2);
            sa2 = fma2(qa[3], k23.y, sa2);  sb2 = fma2(qb[3], k23.y, sb2);
            sa2 = fma2(qa[4], k4,   sa2);   sb2 = fma2(qb[4], k4,   sb2);
            float2 fa = upk2(sa2), fb = upk2(sb2);
            float pa = ex2(fa.x + fa.y);
            float pb = ex2(fb.x + fb.y);
            dena += pa; denb += pb;
            ull ppa = pk2(pa, pa), ppb = pk2(pb, pb);

            ulonglong2 v01 = *(const ulonglong2*)&Vb[j][0];
            ulonglong2 v23 = *(const ulonglong2*)&Vb[j][4];
            ulonglong2 v45 = *(const ulonglong2*)&Vb[j][8];
            acca[0] = fma2(ppa, v01.x, acca[0]);  accb[0] = fma2(ppb, v01.x, accb[0]);
            acca[1] = fma2(ppa, v01.y, acca[1]);  accb[1] = fma2(ppb, v01.y, accb[1]);
            acca[2] = fma2(ppa, v23.x, acca[2]);  accb[2] = fma2(ppb, v23.x, accb[2]);
            acca[3] = fma2(ppa, v23.y, acca[3]);  accb[3] = fma2(ppb, v23.y, accb[3]);
            acca[4] = fma2(ppa, v45.x, acca[4]);  accb[4] = fma2(ppb, v45.x, accb[4]);
            acca[5] = fma2(ppa, v45.y, acca[5]);  accb[5] = fma2(ppb, v45.y, accb[5]);
        }
        __syncthreads();
    }

    // write partials: [z][bh][s][16] = 12 num + den (+3 pad)
    float* oa = g_part + (((size_t)z * (B_ * H_) + bh) * S_ + (q0 + tid)) * 16;
    float* ob = oa + (size_t)128 * 16;
    {
        float2 r0 = upk2(acca[0]), r1 = upk2(acca[1]), r2 = upk2(acca[2]);
        float2 r3 = upk2(acca[3]), r4 = upk2(acca[4]), r5 = upk2(acca[5]);
        *(float4*)(oa + 0)  = make_float4(r0.x, r0.y, r1.x, r1.y);
        *(float4*)(oa + 4)  = make_float4(r2.x, r2.y, r3.x, r3.y);
        *(float4*)(oa + 8)  = make_float4(r4.x, r4.y, r5.x, r5.y);
        *(float4*)(oa + 12) = make_float4(dena, 0.f, 0.f, 0.f);
    }
    {
        float2 r0 = upk2(accb[0]), r1 = upk2(accb[1]), r2 = upk2(accb[2]);
        float2 r3 = upk2(accb[3]), r4 = upk2(accb[4]), r5 = upk2(accb[5]);
        *(float4*)(ob + 0)  = make_float4(r0.x, r0.y, r1.x, r1.y);
        *(float4*)(ob + 4)  = make_float4(r2.x, r2.y, r3.x, r3.y);
        *(float4*)(ob + 8)  = make_float4(r4.x, r4.y, r5.x, r5.y);
        *(float4*)(ob + 12) = make_float4(denb, 0.f, 0.f, 0.f);
    }
}

// ==========================================================================
// Kernel 2b: reduce KSPLIT partials -> g_heads (divide by total den).
// ==========================================================================
__global__ void attn_reduce_kernel()
{
    int idx = blockIdx.x * 256 + threadIdx.x;   // 0 .. 64*2048-1
    int bh = idx >> 11;
    int s  = idx & 2047;
    int b  = bh >> 4, h = bh & 15;

    const size_t zstride = (size_t)(B_ * H_) * S_ * 16;
    const float* r0 = g_part + ((size_t)bh * S_ + s) * 16;

    float n0 = 0.f, n1 = 0.f, n2 = 0.f, n3 = 0.f;
    float n4 = 0.f, n5 = 0.f, n6 = 0.f, n7 = 0.f;
    float n8 = 0.f, n9 = 0.f, n10 = 0.f, n11 = 0.f;
    float den = 0.f;
    #pragma unroll
    for (int zz = 0; zz < KSPLIT; zz++) {
        const float* r = r0 + zz * zstride;
        float4 a0 = *(const float4*)(r + 0);
        float4 a1 = *(const float4*)(r + 4);
        float4 a2 = *(const float4*)(r + 8);
        n0 += a0.x; n1 += a0.y; n2  += a0.z; n3  += a0.w;
        n4 += a1.x; n5 += a1.y; n6  += a1.z; n7  += a1.w;
        n8 += a2.x; n9 += a2.y; n10 += a2.z; n11 += a2.w;
        den += r[12];
    }

    float inv = 1.f / den;
    float* o = g_heads + ((size_t)(b * S_ + s)) * HK + h * DV_;
    *(float4*)(o + 0) = make_float4(n0 * inv, n1 * inv, n2 * inv, n3 * inv);
    *(float4*)(o + 4) = make_float4(n4 * inv, n5 * inv, n6 * inv, n7 * inv);
    *(float4*)(o + 8) = make_float4(n8 * inv, n9 * inv, n10 * inv, n11 * inv);
}

// ==========================================================================
// Kernel 3: output projection on legacy tensor cores (R10 config).
// ==========================================================================
__global__ void __launch_bounds__(128, 4)
outproj_mma_kernel(float* __restrict__ out)
{
    const int m0 = blockIdx.x * 64;
    const int n0 = blockIdx.y * 128;
    const int tid  = threadIdx.x;     // 128
    const int w    = tid >> 5;
    const int lane = tid & 31;

    __shared__ __align__(16) __nv_bfloat16 Ah[64][40];   // 80B stride
    __shared__ __align__(16) __nv_bfloat16 Al[64][40];
    __shared__ __align__(16) __nv_bfloat16 Bh[32][136];  // 272B stride
    __shared__ __align__(16) __nv_bfloat16 Bl[32][136];

    const uint32_t AhB = smem_u32(&Ah[0][0]);
    const uint32_t AlB = smem_u32(&Al[0][0]);
    const uint32_t BhB = smem_u32(&Bh[0][0]);
    const uint32_t BlB = smem_u32(&Bl[0][0]);

    float acc[16][4];
    #pragma unroll
    for (int t = 0; t < 16; t++)
        #pragma unroll
        for (int u = 0; u < 4; u++) acc[t][u] = 0.f;

    for (int k0 = 0; k0 < HK; k0 += 32) {
        #pragma unroll
        for (int l = 0; l < 4; l++) {
            int f   = tid + l * 128;
            int row = f >> 3, c4 = f & 7;
            float4 a = *(const float4*)(g_heads + (size_t)(m0 + row) * HK + k0 + c4 * 4);
            __nv_bfloat16 hx = __float2bfloat16(a.x), hy = __float2bfloat16(a.y);
            __nv_bfloat16 hz = __float2bfloat16(a.z), hw = __float2bfloat16(a.w);
            __nv_bfloat16 lx = __float2bfloat16(a.x - __bfloat162float(hx));
            __nv_bfloat16 ly = __float2bfloat16(a.y - __bfloat162float(hy));
            __nv_bfloat16 lz = __float2bfloat16(a.z - __bfloat162float(hz));
            __nv_bfloat16 lw = __float2bfloat16(a.w - __bfloat162float(hw));
            *(uint32_t*)&Ah[row][c4 * 4 + 0] = bf2u(__nv_bfloat162(hx, hy));
            *(uint32_t*)&Ah[row][c4 * 4 + 2] = bf2u(__nv_bfloat162(hz, hw));
            *(uint32_t*)&Al[row][c4 * 4 + 0] = bf2u(__nv_bfloat162(lx, ly));
            *(uint32_t*)&Al[row][c4 * 4 + 2] = bf2u(__nv_bfloat162(lz, lw));
        }
        #pragma unroll
        for (int l = 0; l < 4; l++) {
            int idx = tid + l * 128;        // 0..511
            int kk  = idx >> 4;             // 16 uint4 per row
            int u   = idx & 15;
            *(uint4*)&Bh[kk][u * 8] = *(const uint4*)(g_wobh + (size_t)(k0 + kk) * D_ + n0 + u * 8);
            *(uint4*)&Bl[kk][u * 8] = *(const uint4*)(g_wobl + (size_t)(k0 + kk) * D_ + n0 + u * 8);
        }
        __syncthreads();

        #pragma unroll
        for (int ks = 0; ks < 2; ks++) {
            uint32_t aoff = (uint32_t)(w * 16 + (lane & 15)) * 80
                          + (uint32_t)(ks * 16 + (lane >> 4) * 8) * 2;
            uint32_t ah[4], al[4];
            ldmx4(ah, AhB + aoff);
            ldmx4(al, AlB + aoff);

            uint32_t brow = (uint32_t)(ks * 16 + ((lane >> 3) & 1) * 8 + (lane & 7));
            uint32_t bbase = brow * 272 + (uint32_t)(lane >> 4) * 16;

            #pragma unroll
            for (int nt = 0; nt < 8; nt++) {
                uint32_t bh[4], bl[4];
                ldmx4t(bh, BhB + bbase + nt * 32);
                ldmx4t(bl, BlB + bbase + nt * 32);
                mma16816(acc[nt * 2 + 0], ah, bh[0], bh[1]);
                mma16816(acc[nt * 2 + 0], al, bh[0], bh[1]);
                mma16816(acc[nt * 2 + 0], ah, bl[0], bl[1]);
                mma16816(acc[nt * 2 + 1], ah, bh[2], bh[3]);
                mma16816(acc[nt * 2 + 1], al, bh[2], bh[3]);
                mma16816(acc[nt * 2 + 1], ah, bl[2], bl[3]);
            }
        }
        __syncthreads();
    }

    const int r0 = m0 + w * 16 + (lane >> 2);
    const int lc = lane & 3;
    #pragma unroll
    for (int t = 0; t < 16; t++) {
        int n = n0 + t * 8 + lc * 2;
        float* o = out + (size_t)r0 * D_ + n;
        *(float2*)o            = make_float2(acc[t][0], acc[t][1]);
        *(float2*)(o + 8 * D_) = make_float2(acc[t][2], acc[t][3]);
    }
}

// ==========================================================================
extern "C" void kernel_launch(void* const* d_in, const int* in_sizes, int n_in,
                              void* d_out, int out_size)
{
    const float* Q  = (const float*)d_in[0];
    const float* K  = (const float*)d_in[1];
    const float* V  = (const float*)d_in[2];
    const float* WQ = (const float*)d_in[3];
    const float* WK = (const float*)d_in[4];
    const float* WV = (const float*)d_in[5];
    const float* WO = (const float*)d_in[6];
    float* out = (float*)d_out;

    pack_w_kernel<<<(3 * D_ * NW) / 256, 256>>>(WQ, WK, WV);
    pack_wo_kernel<<<(HK * D_) / 256, 256>>>(WO);
    proj_mma_kernel<<<dim3(128, 3), 128>>>(Q, K, V);
    attn_kernel<<<dim3(B_ * H_, S_ / 256, KSPLIT), 128>>>();
    attn_reduce_kernel<<<(B_ * H_ * S_) / 256, 256>>>();
    outproj_mma_kernel<<<dim3((B_ * S_) / 64, D_ / 128), 128>>>(out);
}